// round 10
// baseline (speedup 1.0000x reference)
#include <cuda_runtime.h>
#include <cuda_bf16.h>

// Problem shape (fixed by reference setup_inputs): B=8, C=16, H=W=384.
#define BB 8
#define CC 16
#define HW 147456            // 384*384
#define NPLANE (BB*CC)       // 128
#define SPLIT 9              // chunks per plane -> 1152 blocks
#define CHUNK (HW/SPLIT)     // 16384
#define TPB 256
#define NBLK (NPLANE*SPLIT)  // 1152
#define ITERS (CHUNK/4/TPB)  // 16 float4 per thread

#define SMOOTH 1e-6f
#define ALPHA 0.05f

// Per-block partials: [m1, sum_d2, d1, max_t]
__device__ float g_partial[NBLK * 4];
__device__ int   g_counter = 0;   // reset by last block each call

__global__ void __launch_bounds__(TPB, 2)
fused_loss_kernel(const float* __restrict__ net,
                  const float* __restrict__ tgt,
                  const float* __restrict__ mpos,
                  float* __restrict__ out) {
    const int blk   = blockIdx.x;
    const int plane = blk / SPLIT;
    const int chunk = blk - plane * SPLIT;
    const size_t base = (size_t)plane * HW + (size_t)chunk * CHUNK;

    const float4* __restrict__ n4 = (const float4*)(net + base);
    const float4* __restrict__ t4 = (const float4*)(tgt + base);
    const int tid = threadIdx.x;
    const unsigned FULL = 0xFFFFFFFFu;

    float m1 = 0.f, sd = 0.f, d1 = 0.f, mt = 0.f;

#pragma unroll
    for (int i = 0; i < ITERS; i++) {
        const int idx = i * TPB + tid;
        float4 n = __ldcs(&n4[idx]);
        float4 t = __ldcs(&t4[idx]);
        float d, d2;
        d = t.x - n.x; d2 = d * d; sd += d2; m1 += d2 * t.x; d1 += t.x; mt = fmaxf(mt, t.x);
        d = t.y - n.y; d2 = d * d; sd += d2; m1 += d2 * t.y; d1 += t.y; mt = fmaxf(mt, t.y);
        d = t.z - n.z; d2 = d * d; sd += d2; m1 += d2 * t.z; d1 += t.z; mt = fmaxf(mt, t.z);
        d = t.w - n.w; d2 = d * d; sd += d2; m1 += d2 * t.w; d1 += t.w; mt = fmaxf(mt, t.w);
    }

#pragma unroll
    for (int off = 16; off > 0; off >>= 1) {
        m1 += __shfl_down_sync(FULL, m1, off);
        sd += __shfl_down_sync(FULL, sd, off);
        d1 += __shfl_down_sync(FULL, d1, off);
        mt = fmaxf(mt, __shfl_down_sync(FULL, mt, off));
    }

    __shared__ float sh[4][TPB / 32];
    const int lane = tid & 31, wid = tid >> 5;
    if (lane == 0) {
        sh[0][wid] = m1; sh[1][wid] = sd; sh[2][wid] = d1; sh[3][wid] = mt;
    }
    __syncthreads();

    __shared__ bool s_last;
    if (tid == 0) {
        const int NW = TPB / 32;
        float a0 = 0.f, a1 = 0.f, a2 = 0.f, a3 = 0.f;
#pragma unroll
        for (int w = 0; w < NW; w++) {
            a0 += sh[0][w]; a1 += sh[1][w]; a2 += sh[2][w];
            a3 = fmaxf(a3, sh[3][w]);
        }
        float* p = &g_partial[blk * 4];
        p[0] = a0; p[1] = a1; p[2] = a2; p[3] = a3;
        __threadfence();
        int prev = atomicAdd(&g_counter, 1);
        s_last = (prev == NBLK - 1);
    }
    __syncthreads();

    if (!s_last) return;

    // ================= Last block only: finalize =================
    if (tid == 0) g_counter = 0;     // reset for next graph replay
    __threadfence();

    __shared__ float losses[NPLANE];
    __shared__ float smt[NPLANE];
    __shared__ float img[BB];
    __shared__ float s_red[TPB / 32];

    if (tid < NPLANE) {
        float m1f = 0.f, sdf = 0.f, d1f = 0.f, mtf = 0.f;
#pragma unroll
        for (int s = 0; s < SPLIT; s++) {
            const float* p = &g_partial[(tid * SPLIT + s) * 4];
            m1f += p[0]; sdf += p[1]; d1f += p[2]; mtf = fmaxf(mtf, p[3]);
        }
        float m2f = sdf - m1f;
        float d2f = (float)HW - d1f;
        float loss = ALPHA * m1f / (d1f + SMOOTH) + (1.0f - ALPHA) * m2f / (d2f + SMOOTH);
        losses[tid] = loss;          // provisional; may be zeroed below
        smt[tid] = mtf;
    }
    __syncthreads();

    // Fallback (exact reference semantics, never taken for nonzero targets):
    // a plane whose target is all-zero is inactive only if max(mpos)==0 too.
    for (int p = 0; p < NPLANE; p++) {
        if (smt[p] == 0.f) {                 // uniform branch (shared value)
            const float4* __restrict__ p4 = (const float4*)(mpos + (size_t)p * HW);
            float mp = 0.f;
            for (int i = tid; i < HW / 4; i += TPB) {
                float4 v = p4[i];
                mp = fmaxf(mp, fmaxf(fmaxf(v.x, v.y), fmaxf(v.z, v.w)));
            }
#pragma unroll
            for (int off = 16; off > 0; off >>= 1)
                mp = fmaxf(mp, __shfl_down_sync(FULL, mp, off));
            if (lane == 0) s_red[wid] = mp;
            __syncthreads();
            if (tid == 0) {
                float a = 0.f;
#pragma unroll
                for (int w = 0; w < TPB / 32; w++) a = fmaxf(a, s_red[w]);
                if (a == 0.f) losses[p] = 0.f;   // inactive plane
            }
            __syncthreads();
        }
    }

    if (tid < BB) {
        float sum = 0.f;
        int cnt = 0;
#pragma unroll
        for (int c = 0; c < CC; c++) {
            float v = losses[tid * CC + c];
            sum += v;
            cnt += (v != 0.f) ? 1 : 0;
        }
        img[tid] = sum / (float)cnt;
    }
    __syncthreads();

    if (tid == 0) {
        float s = 0.f;
#pragma unroll
        for (int b = 0; b < BB; b++) s += img[b];
        out[0] = s / (float)BB;
    }
}

extern "C" void kernel_launch(void* const* d_in, const int* in_sizes, int n_in,
                              void* d_out, int out_size) {
    const float* net  = (const float*)d_in[0];
    const float* tgt  = (const float*)d_in[1];
    const float* mpos = (const float*)d_in[2];
    float* out = (float*)d_out;

    fused_loss_kernel<<<NBLK, TPB>>>(net, tgt, mpos, out);
}

// round 12
// speedup vs baseline: 1.1363x; 1.1363x over previous
#include <cuda_runtime.h>
#include <cuda_bf16.h>

// Problem shape (fixed by reference setup_inputs): B=8, C=16, H=W=384.
#define BB 8
#define CC 16
#define HW 147456            // 384*384
#define NPLANE (BB*CC)       // 128
#define SPLIT 9              // chunks per plane -> 1152 blocks
#define CHUNK (HW/SPLIT)     // 16384
#define TPB 256
#define NBLK (NPLANE*SPLIT)  // 1152
#define ITERS (CHUNK/4/TPB)  // 16 float4 per thread

#define SMOOTH 1e-6f
#define ALPHA 0.05f

// Per-block partials: [m1, sum_d2, d1, max_t, max_p]
__device__ float g_partial[NBLK * 5];
__device__ int   g_counter = 0;   // reset by last block each call

__global__ void __launch_bounds__(TPB, 2)
fused_loss_kernel(const float* __restrict__ net,
                  const float* __restrict__ tgt,
                  const float* __restrict__ mpos,
                  float* __restrict__ out) {
    const int blk   = blockIdx.x;
    const int plane = blk / SPLIT;
    const int chunk = blk - plane * SPLIT;
    const size_t base = (size_t)plane * HW + (size_t)chunk * CHUNK;

    const float4* __restrict__ n4 = (const float4*)(net + base);
    const float4* __restrict__ t4 = (const float4*)(tgt + base);
    const int tid = threadIdx.x;
    const unsigned FULL = 0xFFFFFFFFu;

    float m1 = 0.f, sd = 0.f, d1 = 0.f, mt = 0.f;

#pragma unroll
    for (int i = 0; i < ITERS; i++) {
        const int idx = i * TPB + tid;
        float4 n = __ldcs(&n4[idx]);
        float4 t = __ldcs(&t4[idx]);
        float d, d2;
        d = t.x - n.x; d2 = d * d; sd += d2; m1 += d2 * t.x; d1 += t.x; mt = fmaxf(mt, t.x);
        d = t.y - n.y; d2 = d * d; sd += d2; m1 += d2 * t.y; d1 += t.y; mt = fmaxf(mt, t.y);
        d = t.z - n.z; d2 = d * d; sd += d2; m1 += d2 * t.z; d1 += t.z; mt = fmaxf(mt, t.z);
        d = t.w - n.w; d2 = d * d; sd += d2; m1 += d2 * t.w; d1 += t.w; mt = fmaxf(mt, t.w);
    }

#pragma unroll
    for (int off = 16; off > 0; off >>= 1) {
        m1 += __shfl_down_sync(FULL, m1, off);
        sd += __shfl_down_sync(FULL, sd, off);
        d1 += __shfl_down_sync(FULL, d1, off);
        mt = fmaxf(mt, __shfl_down_sync(FULL, mt, off));
    }

    __shared__ float sh[4][TPB / 32];
    __shared__ float sh_mp[TPB / 32];
    const int lane = tid & 31, wid = tid >> 5;
    if (lane == 0) {
        sh[0][wid] = m1; sh[1][wid] = sd; sh[2][wid] = d1; sh[3][wid] = mt;
    }

    // Doubles as the barrier for sh[] AND computes "chunk target all-zero".
    // Each lane's post-shuffle mt is a max over a subset covering the chunk,
    // so the block-wide AND of (mt==0) is exact.
    const bool chunk_zero = __syncthreads_and(mt == 0.f);

    // Never taken for nonzero targets. If the whole plane's target is zero,
    // every chunk of it takes this path, so per-plane max over chunk partials
    // equals the true plane mpos max (exact reference semantics).
    if (chunk_zero) {
        const float4* __restrict__ p4 = (const float4*)(mpos + base);
        float mp = 0.f;
#pragma unroll
        for (int i = 0; i < ITERS; i++) {
            float4 v = __ldcs(&p4[i * TPB + tid]);
            mp = fmaxf(mp, fmaxf(fmaxf(v.x, v.y), fmaxf(v.z, v.w)));
        }
#pragma unroll
        for (int off = 16; off > 0; off >>= 1)
            mp = fmaxf(mp, __shfl_down_sync(FULL, mp, off));
        if (lane == 0) sh_mp[wid] = mp;
        __syncthreads();   // uniform branch: legal
    }

    __shared__ bool s_last;
    if (tid == 0) {
        const int NW = TPB / 32;
        float a0 = 0.f, a1 = 0.f, a2 = 0.f, a3 = 0.f, a4 = 0.f;
#pragma unroll
        for (int w = 0; w < NW; w++) {
            a0 += sh[0][w]; a1 += sh[1][w]; a2 += sh[2][w];
            a3 = fmaxf(a3, sh[3][w]);
        }
        if (chunk_zero) {
#pragma unroll
            for (int w = 0; w < NW; w++) a4 = fmaxf(a4, sh_mp[w]);
        }
        float* p = &g_partial[blk * 5];
        p[0] = a0; p[1] = a1; p[2] = a2; p[3] = a3; p[4] = a4;
        __threadfence();
        int prev = atomicAdd(&g_counter, 1);
        s_last = (prev == NBLK - 1);
    }
    __syncthreads();

    if (!s_last) return;

    // ================= Last block only: finalize =================
    if (tid == 0) g_counter = 0;     // reset for next graph replay
    __threadfence();

    __shared__ float losses[NPLANE];
    __shared__ float img[BB];

    if (tid < NPLANE) {
        float m1f = 0.f, sdf = 0.f, d1f = 0.f, mtf = 0.f, mpf = 0.f;
#pragma unroll
        for (int s = 0; s < SPLIT; s++) {
            const float* p = &g_partial[(tid * SPLIT + s) * 5];
            m1f += p[0]; sdf += p[1]; d1f += p[2];
            mtf = fmaxf(mtf, p[3]); mpf = fmaxf(mpf, p[4]);
        }
        float m2f = sdf - m1f;
        float d2f = (float)HW - d1f;
        float loss = ALPHA * m1f / (d1f + SMOOTH) + (1.0f - ALPHA) * m2f / (d2f + SMOOTH);
        bool active = !((mtf == 0.f) && (mpf == 0.f));
        losses[tid] = active ? loss : 0.f;
    }
    __syncthreads();

    if (tid < BB) {
        float sum = 0.f;
        int cnt = 0;
#pragma unroll
        for (int c = 0; c < CC; c++) {
            float v = losses[tid * CC + c];
            sum += v;
            cnt += (v != 0.f) ? 1 : 0;
        }
        img[tid] = sum / (float)cnt;
    }
    __syncthreads();

    if (tid == 0) {
        float s = 0.f;
#pragma unroll
        for (int b = 0; b < BB; b++) s += img[b];
        out[0] = s / (float)BB;
    }
}

extern "C" void kernel_launch(void* const* d_in, const int* in_sizes, int n_in,
                              void* d_out, int out_size) {
    const float* net  = (const float*)d_in[0];
    const float* tgt  = (const float*)d_in[1];
    const float* mpos = (const float*)d_in[2];
    float* out = (float*)d_out;

    fused_loss_kernel<<<NBLK, TPB>>>(net, tgt, mpos, out);
}

// round 13
// speedup vs baseline: 1.2657x; 1.1139x over previous
#include <cuda_runtime.h>
#include <cuda_bf16.h>

// Problem shape (fixed by reference setup_inputs): B=8, C=16, H=W=384.
#define BB 8
#define CC 16
#define HW 147456            // 384*384
#define NPLANE (BB*CC)       // 128
#define SPLIT 6              // chunks per plane -> 768 blocks
#define CHUNK (HW/SPLIT)     // 24576
#define TPB 256
#define NBLK (NPLANE*SPLIT)  // 768
#define ITERS (CHUNK/4/TPB)  // 24 float4 per thread -> 48 LDG.128 in flight

#define SMOOTH 1e-6f
#define ALPHA 0.05f

// Per-block partials: [m1, sum_d2, d1, max_t, max_p]
__device__ float g_partial[NBLK * 5];
__device__ int   g_counter = 0;   // reset by last block each call

__global__ void __launch_bounds__(TPB, 2)
fused_loss_kernel(const float* __restrict__ net,
                  const float* __restrict__ tgt,
                  const float* __restrict__ mpos,
                  float* __restrict__ out) {
    const int blk   = blockIdx.x;
    const int plane = blk / SPLIT;
    const int chunk = blk - plane * SPLIT;
    const size_t base = (size_t)plane * HW + (size_t)chunk * CHUNK;

    const float4* __restrict__ n4 = (const float4*)(net + base);
    const float4* __restrict__ t4 = (const float4*)(tgt + base);
    const int tid = threadIdx.x;
    const unsigned FULL = 0xFFFFFFFFu;

    float m1 = 0.f, sd = 0.f, d1 = 0.f, mt = 0.f;

#pragma unroll
    for (int i = 0; i < ITERS; i++) {
        const int idx = i * TPB + tid;
        float4 n = __ldcs(&n4[idx]);
        float4 t = __ldcs(&t4[idx]);
        float d, d2;
        d = t.x - n.x; d2 = d * d; sd += d2; m1 += d2 * t.x; d1 += t.x; mt = fmaxf(mt, t.x);
        d = t.y - n.y; d2 = d * d; sd += d2; m1 += d2 * t.y; d1 += t.y; mt = fmaxf(mt, t.y);
        d = t.z - n.z; d2 = d * d; sd += d2; m1 += d2 * t.z; d1 += t.z; mt = fmaxf(mt, t.z);
        d = t.w - n.w; d2 = d * d; sd += d2; m1 += d2 * t.w; d1 += t.w; mt = fmaxf(mt, t.w);
    }

#pragma unroll
    for (int off = 16; off > 0; off >>= 1) {
        m1 += __shfl_down_sync(FULL, m1, off);
        sd += __shfl_down_sync(FULL, sd, off);
        d1 += __shfl_down_sync(FULL, d1, off);
        mt = fmaxf(mt, __shfl_down_sync(FULL, mt, off));
    }

    __shared__ float sh[4][TPB / 32];
    __shared__ float sh_mp[TPB / 32];
    const int lane = tid & 31, wid = tid >> 5;
    if (lane == 0) {
        sh[0][wid] = m1; sh[1][wid] = sd; sh[2][wid] = d1; sh[3][wid] = mt;
    }

    // Doubles as the barrier for sh[] AND computes "chunk target all-zero".
    const bool chunk_zero = __syncthreads_and(mt == 0.f);

    // Never taken for nonzero targets. If the whole plane's target is zero,
    // every chunk of it takes this path, so per-plane max over chunk partials
    // equals the true plane mpos max (exact reference semantics).
    if (chunk_zero) {
        const float4* __restrict__ p4 = (const float4*)(mpos + base);
        float mp = 0.f;
#pragma unroll
        for (int i = 0; i < ITERS; i++) {
            float4 v = __ldcs(&p4[i * TPB + tid]);
            mp = fmaxf(mp, fmaxf(fmaxf(v.x, v.y), fmaxf(v.z, v.w)));
        }
#pragma unroll
        for (int off = 16; off > 0; off >>= 1)
            mp = fmaxf(mp, __shfl_down_sync(FULL, mp, off));
        if (lane == 0) sh_mp[wid] = mp;
        __syncthreads();   // uniform branch: legal
    }

    __shared__ bool s_last;
    if (tid == 0) {
        const int NW = TPB / 32;
        float a0 = 0.f, a1 = 0.f, a2 = 0.f, a3 = 0.f, a4 = 0.f;
#pragma unroll
        for (int w = 0; w < NW; w++) {
            a0 += sh[0][w]; a1 += sh[1][w]; a2 += sh[2][w];
            a3 = fmaxf(a3, sh[3][w]);
        }
        if (chunk_zero) {
#pragma unroll
            for (int w = 0; w < NW; w++) a4 = fmaxf(a4, sh_mp[w]);
        }
        float* p = &g_partial[blk * 5];
        p[0] = a0; p[1] = a1; p[2] = a2; p[3] = a3; p[4] = a4;
        __threadfence();
        int prev = atomicAdd(&g_counter, 1);
        s_last = (prev == NBLK - 1);
    }
    __syncthreads();

    if (!s_last) return;

    // ================= Last block only: finalize =================
    if (tid == 0) g_counter = 0;     // reset for next graph replay
    __threadfence();

    __shared__ float losses[NPLANE];
    __shared__ float img[BB];

    if (tid < NPLANE) {
        float m1f = 0.f, sdf = 0.f, d1f = 0.f, mtf = 0.f, mpf = 0.f;
#pragma unroll
        for (int s = 0; s < SPLIT; s++) {
            const float* p = &g_partial[(tid * SPLIT + s) * 5];
            m1f += p[0]; sdf += p[1]; d1f += p[2];
            mtf = fmaxf(mtf, p[3]); mpf = fmaxf(mpf, p[4]);
        }
        float m2f = sdf - m1f;
        float d2f = (float)HW - d1f;
        float loss = ALPHA * m1f / (d1f + SMOOTH) + (1.0f - ALPHA) * m2f / (d2f + SMOOTH);
        bool active = !((mtf == 0.f) && (mpf == 0.f));
        losses[tid] = active ? loss : 0.f;
    }
    __syncthreads();

    if (tid < BB) {
        float sum = 0.f;
        int cnt = 0;
#pragma unroll
        for (int c = 0; c < CC; c++) {
            float v = losses[tid * CC + c];
            sum += v;
            cnt += (v != 0.f) ? 1 : 0;
        }
        img[tid] = sum / (float)cnt;
    }
    __syncthreads();

    if (tid == 0) {
        float s = 0.f;
#pragma unroll
        for (int b = 0; b < BB; b++) s += img[b];
        out[0] = s / (float)BB;
    }
}

extern "C" void kernel_launch(void* const* d_in, const int* in_sizes, int n_in,
                              void* d_out, int out_size) {
    const float* net  = (const float*)d_in[0];
    const float* tgt  = (const float*)d_in[1];
    const float* mpos = (const float*)d_in[2];
    float* out = (float*)d_out;

    fused_loss_kernel<<<NBLK, TPB>>>(net, tgt, mpos, out);
}